// round 5
// baseline (speedup 1.0000x reference)
#include <cuda_runtime.h>
#include <math.h>

// Problem constants (fixed shapes per reference)
#define N_NODES 100000
#define N_EDGES 1600000
#define F_IN    256
#define F_OUT   128
#define ALPHA   0.2f

// ---------------- device scratch (static; no allocation allowed) ----------------
__device__ float g_h[(size_t)N_NODES * F_OUT];   // 51.2 MB: h = x @ W
__device__ float g_sl[N_NODES];                  // score_l per node
__device__ float g_sr[N_NODES];                  // score_r per node
__device__ int   g_deg[N_NODES];                 // in-degree histogram
__device__ int   g_off[N_NODES + 1];             // CSR offsets (exclusive scan)
__device__ int   g_cur[N_NODES];                 // fill cursors
__device__ int   g_src[N_EDGES];                 // CSR: src node per slot
__device__ int   g_is64;                         // edge_index dtype flag

// ---------------- warp reduction helpers ----------------
__device__ __forceinline__ float warpMax(float v) {
#pragma unroll
    for (int o = 16; o > 0; o >>= 1) v = fmaxf(v, __shfl_xor_sync(0xffffffffu, v, o));
    return v;
}
__device__ __forceinline__ float warpSum(float v) {
#pragma unroll
    for (int o = 16; o > 0; o >>= 1) v += __shfl_xor_sync(0xffffffffu, v, o);
    return v;
}

// ---------------- 0) edge dtype detection ----------------
// int64 little-endian with values < 2^31 has zero hi-words at odd int32 slots.
__global__ void detect_kernel(const int* __restrict__ p) {
    int lane = threadIdx.x;
    int bad = 0;
    for (int k = lane; k < 256; k += 32)
        if (p[2 * k + 1] != 0) bad = 1;
    unsigned b = __ballot_sync(0xffffffffu, bad);
    if (lane == 0) g_is64 = (b == 0) ? 1 : 0;
}

__device__ __forceinline__ int edge_at(const void* eidx, long long elem) {
    if (g_is64) return (int)((const long long*)eidx)[elem];
    return ((const int*)eidx)[elem];
}

// ---------------- 1) GEMM: h = x @ W (fp32) + fused attention scores ----------------
// Block tile 128 rows x 128 cols, 256 threads, each thread 8x8.
// A staged TRANSPOSED in smem so inner loop uses LDS.128 for both operands.
#define KC2 16
__global__ __launch_bounds__(256) void gemm_kernel(
    const float* __restrict__ x, const float* __restrict__ w,
    const float* __restrict__ a_l, const float* __restrict__ a_r, int n)
{
    __shared__ __align__(16) float As[KC2][132];   // [k][row], padded
    __shared__ __align__(16) float Bs[KC2][128];   // [k][col]

    const int tid = threadIdx.x;
    const int tx  = tid & 15;    // col group: cols tx*8 .. tx*8+7
    const int ty  = tid >> 4;    // row group: rows ty*8 .. ty*8+7
    const int rowBase = blockIdx.x * 128;

    float acc[8][8];
#pragma unroll
    for (int i = 0; i < 8; i++)
#pragma unroll
        for (int j = 0; j < 8; j++) acc[i][j] = 0.f;

    for (int k0 = 0; k0 < F_IN; k0 += KC2) {
        // A tile: 128 rows x 16 k = 512 float4 loads, 2 per thread, transposed store
#pragma unroll
        for (int l = 0; l < 2; l++) {
            int idx = tid + l * 256;       // 0..511
            int r   = idx >> 2;            // row 0..127
            int c4  = idx & 3;             // k quad
            float4 v = make_float4(0.f, 0.f, 0.f, 0.f);
            int gr = rowBase + r;
            if (gr < n)
                v = *(const float4*)(x + (size_t)gr * F_IN + k0 + c4 * 4);
            As[c4 * 4 + 0][r] = v.x;
            As[c4 * 4 + 1][r] = v.y;
            As[c4 * 4 + 2][r] = v.z;
            As[c4 * 4 + 3][r] = v.w;
        }
        // B tile: 16 x 128 = 512 float4 loads, 2 per thread
#pragma unroll
        for (int l = 0; l < 2; l++) {
            int idx = tid + l * 256;
            int r   = idx >> 5;            // k row 0..15
            int c4  = idx & 31;            // col quad
            *(float4*)&Bs[r][c4 * 4] =
                *(const float4*)(w + (size_t)(k0 + r) * F_OUT + c4 * 4);
        }
        __syncthreads();

#pragma unroll
        for (int k = 0; k < KC2; k++) {
            float4 a0 = *(const float4*)&As[k][ty * 8];
            float4 a1 = *(const float4*)&As[k][ty * 8 + 4];
            float4 b0 = *(const float4*)&Bs[k][tx * 8];
            float4 b1 = *(const float4*)&Bs[k][tx * 8 + 4];
            float a[8] = {a0.x, a0.y, a0.z, a0.w, a1.x, a1.y, a1.z, a1.w};
            float b[8] = {b0.x, b0.y, b0.z, b0.w, b1.x, b1.y, b1.z, b1.w};
#pragma unroll
            for (int i = 0; i < 8; i++)
#pragma unroll
                for (int j = 0; j < 8; j++) acc[i][j] += a[i] * b[j];
        }
        __syncthreads();
    }

    // epilogue: store h + fused scores (row dot a_l / a_r, reduce over tx lanes)
    float al[8], ar[8];
#pragma unroll
    for (int j = 0; j < 8; j++) { al[j] = a_l[tx * 8 + j]; ar[j] = a_r[tx * 8 + j]; }

#pragma unroll
    for (int i = 0; i < 8; i++) {
        int gr = rowBase + ty * 8 + i;
        float pl = 0.f, pr = 0.f;
#pragma unroll
        for (int j = 0; j < 8; j++) { pl += acc[i][j] * al[j]; pr += acc[i][j] * ar[j]; }
        // reduce across the 16 tx lanes (lane = (ty&1)*16 + tx; xor<16 stays in group)
#pragma unroll
        for (int o = 1; o < 16; o <<= 1) {
            pl += __shfl_xor_sync(0xffffffffu, pl, o);
            pr += __shfl_xor_sync(0xffffffffu, pr, o);
        }
        if (gr < n) {
            *(float4*)(g_h + (size_t)gr * F_OUT + tx * 8) =
                make_float4(acc[i][0], acc[i][1], acc[i][2], acc[i][3]);
            *(float4*)(g_h + (size_t)gr * F_OUT + tx * 8 + 4) =
                make_float4(acc[i][4], acc[i][5], acc[i][6], acc[i][7]);
            if (tx == 0) { g_sl[gr] = pl; g_sr[gr] = pr; }
        }
    }
}

// ---------------- 2) CSR build ----------------
__global__ void zero_deg_kernel(int n) {
    int i = blockIdx.x * blockDim.x + threadIdx.x;
    if (i < n) g_deg[i] = 0;
}

__global__ void hist_kernel(const void* __restrict__ eidx, int e) {
    int i = blockIdx.x * blockDim.x + threadIdx.x;
    if (i < e) atomicAdd(&g_deg[edge_at(eidx, i)], 1);
}

// Single-block exclusive scan of g_deg -> g_off, g_cur (grid=1, block=1024)
__global__ __launch_bounds__(1024) void scan_kernel(int n) {
    __shared__ int sh_warp[32];
    __shared__ int sh_total;
    const int tid  = threadIdx.x;
    const int lane = tid & 31;
    const int wid  = tid >> 5;
    int running = 0;
    for (int base = 0; base < n; base += 1024) {
        int i = base + tid;
        int v = (i < n) ? g_deg[i] : 0;
        int incl = v;
#pragma unroll
        for (int o = 1; o < 32; o <<= 1) {
            int t = __shfl_up_sync(0xffffffffu, incl, o);
            if (lane >= o) incl += t;
        }
        if (lane == 31) sh_warp[wid] = incl;
        __syncthreads();
        if (tid < 32) {
            int ws = sh_warp[tid];
            int wi = ws;
#pragma unroll
            for (int o = 1; o < 32; o <<= 1) {
                int t = __shfl_up_sync(0xffffffffu, wi, o);
                if (tid >= o) wi += t;
            }
            sh_warp[tid] = wi - ws;   // exclusive warp offset
        }
        __syncthreads();
        int excl = incl - v + sh_warp[wid];
        if (i < n) { g_off[i] = running + excl; g_cur[i] = running + excl; }
        if (tid == 1023) sh_total = excl + v;   // chunk total
        __syncthreads();
        running += sh_total;
        __syncthreads();
    }
    if (tid == 0) g_off[n] = running;
}

__global__ void fill_kernel(const void* __restrict__ eidx, int e) {
    int i = blockIdx.x * blockDim.x + threadIdx.x;
    if (i < e) {
        int r = edge_at(eidx, i);                    // dst
        int c = edge_at(eidx, (long long)e + i);     // src
        int p = atomicAdd(&g_cur[r], 1);
        g_src[p] = c;
    }
}

// ---------------- 3) fused softmax + SpMM + bias + gated encoder ----------------
// One warp per destination node: 3 streaming passes (max / sum / weighted acc).
__global__ __launch_bounds__(256) void aggregate_kernel(
    const float* __restrict__ bias, const float* __restrict__ fc,
    const float* __restrict__ bf, float* __restrict__ out, int n)
{
    const int node = (blockIdx.x * blockDim.x + threadIdx.x) >> 5;
    const int lane = threadIdx.x & 31;
    if (node >= n) return;

    const int s = g_off[node];
    const int e = g_off[node + 1];
    const float sl = g_sl[node];

    // pass 1: segment max
    float m = -INFINITY;
    for (int j = s + lane; j < e; j += 32) {
        int c = g_src[j];
        float v = sl + g_sr[c];
        v = v > 0.f ? v : ALPHA * v;
        m = fmaxf(m, v);
    }
    m = warpMax(m);

    // pass 2: segment sum of exp
    float sum = 0.f;
    for (int j = s + lane; j < e; j += 32) {
        int c = g_src[j];
        float v = sl + g_sr[c];
        v = v > 0.f ? v : ALPHA * v;
        sum += __expf(v - m);
    }
    sum = warpSum(sum);
    const float inv = 1.f / (sum + 1e-16f);

    // pass 3: weighted accumulation of h[src] rows (lane owns 4 features)
    float4 acc = make_float4(0.f, 0.f, 0.f, 0.f);
    for (int j0 = s; j0 < e; j0 += 32) {
        int   j = j0 + lane;
        int   c = 0;
        float w = 0.f;
        if (j < e) {
            c = g_src[j];
            float v = sl + g_sr[c];
            v = v > 0.f ? v : ALPHA * v;
            w = __expf(v - m) * inv;
        }
        int cnt = min(32, e - j0);
        for (int t = 0; t < cnt; t++) {
            int   cc = __shfl_sync(0xffffffffu, c, t);
            float ww = __shfl_sync(0xffffffffu, w, t);
            const float4 hv = *(const float4*)(g_h + (size_t)cc * F_OUT + lane * 4);
            acc.x += ww * hv.x;
            acc.y += ww * hv.y;
            acc.z += ww * hv.z;
            acc.w += ww * hv.w;
        }
    }

    // epilogue: + bias, sigmoid gate, relu(v) + gate*min(v,0)
    float4 bsv = *(const float4*)(bias + lane * 4);
    float4 v = make_float4(acc.x + bsv.x, acc.y + bsv.y, acc.z + bsv.z, acc.w + bsv.w);
    float4 fv = *(const float4*)(fc + lane * 4);
    float p = v.x * fv.x + v.y * fv.y + v.z * fv.z + v.w * fv.w;
    p = warpSum(p) + bf[0];
    float gate = 1.f / (1.f + __expf(-p));

    float4 o;
    o.x = (v.x < 0.f ? 0.f : v.x) + gate * (v.x > 0.f ? 0.f : v.x);
    o.y = (v.y < 0.f ? 0.f : v.y) + gate * (v.y > 0.f ? 0.f : v.y);
    o.z = (v.z < 0.f ? 0.f : v.z) + gate * (v.z > 0.f ? 0.f : v.z);
    o.w = (v.w < 0.f ? 0.f : v.w) + gate * (v.w > 0.f ? 0.f : v.w);
    *(float4*)(out + (size_t)node * F_OUT + lane * 4) = o;
}

// ---------------- launch ----------------
extern "C" void kernel_launch(void* const* d_in, const int* in_sizes, int n_in,
                              void* d_out, int out_size)
{
    const float* x      = (const float*)d_in[0];
    const void*  eidx   = d_in[1];               // [2, E]; int32 or int64 (detected)
    // d_in[2] = edge_attr (unused by the reference)
    const float* weight = (const float*)d_in[3];
    const float* bias   = (const float*)d_in[4];
    const float* a_l    = (const float*)d_in[5];
    const float* a_r    = (const float*)d_in[6];
    const float* fc     = (const float*)d_in[7];
    const float* bf     = (const float*)d_in[8];
    float*       out    = (float*)d_out;

    const int n = in_sizes[0] / F_IN;    // 100000
    const int e = in_sizes[1] / 2;       // 1600000 (element count is 2E for either dtype)

    // 0) dtype sniff (must precede edge kernels; same stream = ordered)
    detect_kernel<<<1, 32>>>((const int*)eidx);
    // 1) h = x @ W  (+ fused per-node scores)
    gemm_kernel<<<(n + 127) / 128, 256>>>(x, weight, a_l, a_r, n);
    // 2) CSR build
    zero_deg_kernel<<<(n + 255) / 256, 256>>>(n);
    hist_kernel<<<(e + 255) / 256, 256>>>(eidx, e);
    scan_kernel<<<1, 1024>>>(n);
    fill_kernel<<<(e + 255) / 256, 256>>>(eidx, e);
    // 3) fused softmax + SpMM + encoder
    aggregate_kernel<<<(n + 7) / 8, 256>>>(bias, fc, bf, out, n);
}